// round 14
// baseline (speedup 1.0000x reference)
#include <cuda_runtime.h>

typedef unsigned long long u64;

#define NTHREADS 512
#define NBLOCKS  4096

#define RAW_S 72    // 16B-aligned rows
#define HB_S  72

__device__ unsigned g_max_bits;   // zero-init; re-zeroed by last block each call
__device__ unsigned g_done;
__device__ unsigned g_max_final;

__device__ __forceinline__ u64 pk2(float x, float y){ u64 r; asm("mov.b64 %0,{%1,%2};":"=l"(r):"f"(x),"f"(y)); return r; }
__device__ __forceinline__ void unpk2(u64 v, float& x, float& y){ asm("mov.b64 {%0,%1},%2;":"=f"(x),"=f"(y):"l"(v)); }
__device__ __forceinline__ u64 add2(u64 a, u64 b){ u64 d; asm("add.rn.f32x2 %0,%1,%2;":"=l"(d):"l"(a),"l"(b)); return d; }
__device__ __forceinline__ u64 mul2(u64 a, u64 b){ u64 d; asm("mul.rn.f32x2 %0,%1,%2;":"=l"(d):"l"(a),"l"(b)); return d; }
__device__ __forceinline__ u64 fma2(u64 a, u64 b, u64 c){ u64 d; asm("fma.rn.f32x2 %0,%1,%2,%3;":"=l"(d):"l"(a),"l"(b),"l"(c)); return d; }
__device__ __forceinline__ u64 lds2(const float* p){ return *(const u64*)p; }
__device__ __forceinline__ void sts2(float* p, u64 v){ *(u64*)p = v; }

__device__ __forceinline__ void cp16(unsigned dst, const float* src, int sz){
    asm volatile("cp.async.cg.shared.global [%0], [%1], 16, %2;"
                 :: "r"(dst), "l"(src), "r"(sz));
}

__global__ void __launch_bounds__(NTHREADS, 3) edge_pass1(
    const float* __restrict__ img,
    const float* __restrict__ gauss,
    const float* __restrict__ sobel,
    float* __restrict__ out)
{
    __shared__ float s_raw[3][38 * RAW_S];  // triple-buffered: img cols bx-4..bx+67
    __shared__ float s_hb [38 * HB_S];      // h-gauss, cc=0..65 -> img col bx-1+cc
    __shared__ float s_halo[32 * 4];        // per row: {t1.lo,t1.hi,t2.lo,t2.hi} for pair cc=64
    __shared__ float s_red[16];

    const int tid = threadIdx.x;
    const int bx = blockIdx.x << 6;
    const int by = blockIdx.y << 5;
    const int b  = blockIdx.z;
    const bool interior = (blockIdx.x - 1u < 6u) && (blockIdx.y - 1u < 14u);

    // gauss symmetric: g3=g1, g4=g0; sobel = [1,2,1]^T x [1,0,-1]
    const float g0 = __ldg(gauss + 0), g1 = __ldg(gauss + 1), g2 = __ldg(gauss + 2);
    const u64 g0p = pk2(g0, g0), g1p = pk2(g1, g1), g2p = pk2(g2, g2);
    const u64 m1p = pk2(-1.f, -1.f);

    const float* img_b = img + (((size_t)(b * 3)) << 18);

    auto load_raw = [&](int c) {
        unsigned rbase = (unsigned)__cvta_generic_to_shared(&s_raw[c][0]);
        const float* src = img_b + (((size_t)c) << 18);
        if (interior) {
            const float* base = src + ((by - 3) << 9) + bx - 4;
            #pragma unroll 2
            for (int i = tid; i < 684; i += NTHREADS) {
                int ry = i / 18, m = i - ry * 18;
                cp16(rbase + (unsigned)(ry * RAW_S + 4 * m) * 4u, base + (ry << 9) + 4 * m, 16);
            }
        } else {
            #pragma unroll 2
            for (int i = tid; i < 684; i += NTHREADS) {
                int ry = i / 18, m = i - ry * 18;
                int gy = by + ry - 3, gc = bx - 4 + 4 * m;
                bool ok = ((unsigned)gy < 512u) && ((unsigned)gc < 509u);
                const float* sp = ok ? (src + (gy << 9) + gc) : src;
                cp16(rbase + (unsigned)(ry * RAW_S + 4 * m) * 4u, sp, ok ? 16 : 0);
            }
        }
        asm volatile("cp.async.commit_group;");
    };

    // main fused-task mapping (tid < 256): warp w -> rows 4w..4w+3, lane l -> pair (2l, 2l+1)
    const int l  = tid & 31;
    const int r0 = (tid >> 5) << 2;         // 0..28 for tid<256
    const int cb = l << 1;                  // 0..62

    u64 acc0 = 0ull, acc1 = 0ull, acc2 = 0ull, acc3 = 0ull;   // rows r0..r0+3, packed cols

    // blur one hb row-window with crop: s = gauss5(h[j..j+4]) masked
    auto blur1 = [&](const u64* h, int j, int rbase_, u64 cm) -> u64 {
        u64 s = fma2(g0p, add2(h[j], h[j + 4]),
                fma2(g1p, add2(h[j + 1], h[j + 3]), mul2(g2p, h[j + 2])));
        if (!interior) {
            s = mul2(s, cm);
            if ((unsigned)(by + rbase_ - 1 + j) >= 512u) s = 0ull;
        }
        return s;
    };

    // prologue: issue ALL channel loads (3 groups outstanding)
    load_raw(0); load_raw(1); load_raw(2);

    #pragma unroll 1
    for (int c = 0; c < 3; c++) {
        if (c == 0)      asm volatile("cp.async.wait_group 2;");
        else if (c == 1) asm volatile("cp.async.wait_group 1;");
        else             asm volatile("cp.async.wait_group 0;");
        __syncthreads();          // bar1: raw[c] visible; prior fused reads of s_hb complete

        // ---- stage 2: horizontal gaussian -> s_hb[38][66] ----
        if (tid < 418) {
            int ry = tid / 11;
            int c0 = (tid - ry * 11) * 6;
            const float* rp = &s_raw[c][0] + ry * RAW_S + c0;
            float wv[12];
            #pragma unroll
            for (int u = 0; u < 6; u++) {
                float2 t = *(const float2*)(rp + 2 * u);
                wv[2 * u] = t.x; wv[2 * u + 1] = t.y;
            }
            float o[6];
            #pragma unroll
            for (int j = 0; j < 6; j++)
                o[j] = fmaf(g0, wv[j + 1] + wv[j + 5],
                       fmaf(g1, wv[j + 2] + wv[j + 4], g2 * wv[j + 3]));
            float* hp = s_hb + ry * HB_S + c0;
            *(float2*)(hp)     = make_float2(o[0], o[1]);
            *(float2*)(hp + 2) = make_float2(o[2], o[3]);
            *(float2*)(hp + 4) = make_float2(o[4], o[5]);
        }
        __syncthreads();          // bar2: hb(c) visible

        // ---- fused S3+S4 (warps 0..8 participate in named barrier) ----
        if (tid < 288) {
            u64 tA1a, tA2a, tA1b, tA2b;
            u64 h[10], bl[6];
            u64 cm = 0;
            const float* hp = s_hb + r0 * HB_S + cb;

            if (tid < 256) {
                // half A taps: rows r0, r0+1 (needs hb rows r0..r0+7)
                #pragma unroll
                for (int k = 0; k < 8; k++) h[k] = lds2(hp + k * HB_S);
                if (!interior)
                    cm = pk2(((unsigned)(bx + cb - 1) < 512u) ? 1.f : 0.f,
                             ((unsigned)(bx + cb)     < 512u) ? 1.f : 0.f);
                #pragma unroll
                for (int j = 0; j < 4; j++) bl[j] = blur1(h, j, r0, cm);
                tA1a = add2(add2(bl[0], bl[2]), add2(bl[1], bl[1]));
                tA2a = fma2(bl[2], m1p, bl[0]);
                tA1b = add2(add2(bl[1], bl[3]), add2(bl[2], bl[2]));
                tA2b = fma2(bl[3], m1p, bl[1]);
            } else if (tid < 264) {
                // tail: pair cc=64 taps for rows q0..q0+3 -> s_halo (chunked, low regs)
                int q0 = (tid - 256) << 2;
                const float* xp = s_hb + q0 * HB_S + 64;
                u64 xh[10], xb[6];
                #pragma unroll
                for (int k = 0; k < 10; k++) xh[k] = lds2(xp + k * HB_S);
                u64 xcm = 0;
                if (!interior)
                    xcm = pk2(1.f, ((unsigned)(bx + 64) < 512u) ? 1.f : 0.f);
                #pragma unroll
                for (int j = 0; j < 6; j++) xb[j] = blur1(xh, j, q0, xcm);
                #pragma unroll
                for (int i = 0; i < 4; i++) {
                    u64 t1 = add2(add2(xb[i], xb[i + 2]), add2(xb[i + 1], xb[i + 1]));
                    u64 t2 = fma2(xb[i + 2], m1p, xb[i]);
                    sts2(&s_halo[(q0 + i) * 4],     t1);
                    sts2(&s_halo[(q0 + i) * 4 + 2], t2);
                }
            }
            asm volatile("bar.sync 1, 288;" ::: "memory");   // halo visible to warps 0..7

            if (tid < 256) {
                // ---- half A consume: shuffle neighbor taps, accumulate rows r0, r0+1 ----
                u64 n1a = __shfl_down_sync(0xffffffffu, tA1a, 1);
                u64 n2a = __shfl_down_sync(0xffffffffu, tA2a, 1);
                u64 n1b = __shfl_down_sync(0xffffffffu, tA1b, 1);
                u64 n2b = __shfl_down_sync(0xffffffffu, tA2b, 1);
                if (l == 31) {
                    n1a = lds2(&s_halo[r0 * 4]);       n2a = lds2(&s_halo[r0 * 4 + 2]);
                    n1b = lds2(&s_halo[(r0+1) * 4]);   n2b = lds2(&s_halo[(r0+1) * 4 + 2]);
                }
                {
                    u64 gx = fma2(n1a, m1p, tA1a);
                    float ahi_, alo_, bhi_, blo_;
                    unpk2(tA2a, alo_, ahi_); unpk2(n2a, blo_, bhi_);
                    u64 M = pk2(ahi_, blo_);
                    u64 gy = add2(add2(tA2a, n2a), add2(M, M));
                    acc0 = fma2(gx, gx, fma2(gy, gy, acc0));
                }
                {
                    u64 gx = fma2(n1b, m1p, tA1b);
                    float ahi_, alo_, bhi_, blo_;
                    unpk2(tA2b, alo_, ahi_); unpk2(n2b, blo_, bhi_);
                    u64 M = pk2(ahi_, blo_);
                    u64 gy = add2(add2(tA2b, n2b), add2(M, M));
                    acc1 = fma2(gx, gx, fma2(gy, gy, acc1));
                }

                // ---- half B: rows r0+2, r0+3 (needs hb rows r0+2..r0+9; h[4..7], bl[2..3] live) ----
                h[8] = lds2(hp + 8 * HB_S);
                h[9] = lds2(hp + 9 * HB_S);
                bl[4] = blur1(h, 4, r0, cm);
                bl[5] = blur1(h, 5, r0, cm);
                u64 tB1a = add2(add2(bl[2], bl[4]), add2(bl[3], bl[3]));
                u64 tB2a = fma2(bl[4], m1p, bl[2]);
                u64 tB1b = add2(add2(bl[3], bl[5]), add2(bl[4], bl[4]));
                u64 tB2b = fma2(bl[5], m1p, bl[3]);

                u64 n1c = __shfl_down_sync(0xffffffffu, tB1a, 1);
                u64 n2c = __shfl_down_sync(0xffffffffu, tB2a, 1);
                u64 n1d = __shfl_down_sync(0xffffffffu, tB1b, 1);
                u64 n2d = __shfl_down_sync(0xffffffffu, tB2b, 1);
                if (l == 31) {
                    n1c = lds2(&s_halo[(r0+2) * 4]);   n2c = lds2(&s_halo[(r0+2) * 4 + 2]);
                    n1d = lds2(&s_halo[(r0+3) * 4]);   n2d = lds2(&s_halo[(r0+3) * 4 + 2]);
                }
                {
                    u64 gx = fma2(n1c, m1p, tB1a);
                    float ahi_, alo_, bhi_, blo_;
                    unpk2(tB2a, alo_, ahi_); unpk2(n2c, blo_, bhi_);
                    u64 M = pk2(ahi_, blo_);
                    u64 gy = add2(add2(tB2a, n2c), add2(M, M));
                    acc2 = fma2(gx, gx, fma2(gy, gy, acc2));
                }
                {
                    u64 gx = fma2(n1d, m1p, tB1b);
                    float ahi_, alo_, bhi_, blo_;
                    unpk2(tB2b, alo_, ahi_); unpk2(n2d, blo_, bhi_);
                    u64 M = pk2(ahi_, blo_);
                    u64 gy = add2(add2(tB2b, n2d), add2(M, M));
                    acc3 = fma2(gx, gx, fma2(gy, gy, acc3));
                }
            }
        }
    }

    // ---- magnitude, store (4 rows x float2), block max ----
    float mloc = 0.f;
    if (tid < 256) {
        size_t base = (((size_t)((b << 9) + by + r0)) << 9) + bx + cb;
        u64 ap[4] = {acc0, acc1, acc2, acc3};
        #pragma unroll
        for (int i = 0; i < 4; i++) {
            float x, y; unpk2(ap[i], x, y);
            float mx = sqrtf(x), my = sqrtf(y);
            *(float2*)(out + base + (size_t)i * 512) = make_float2(mx, my);
            mloc = fmaxf(mloc, fmaxf(mx, my));
        }
    }
    #pragma unroll
    for (int o = 16; o; o >>= 1) mloc = fmaxf(mloc, __shfl_xor_sync(0xffffffffu, mloc, o));
    if ((tid & 31) == 0) s_red[tid >> 5] = mloc;
    __syncthreads();
    if (tid == 0) {
        float m = s_red[0];
        #pragma unroll
        for (int k = 1; k < 16; k++) m = fmaxf(m, s_red[k]);
        atomicMax(&g_max_bits, __float_as_uint(m));
        __threadfence();
        unsigned o = atomicAdd(&g_done, 1u);
        if (o == NBLOCKS - 1u) {
            g_max_final = g_max_bits;   // publish for normalize
            g_max_bits = 0u;            // reset for next graph replay
            g_done = 0u;
            __threadfence();
        }
    }
}

__global__ void __launch_bounds__(256) normalize_kernel(float* __restrict__ out)
{
    const float inv = 1.0f / __uint_as_float(g_max_final);
    float4* p = (float4*)out;
    int i = blockIdx.x * 256 + threadIdx.x;   // 8192 * 256 = 2^21 float4 exactly
    float4 v = p[i];
    v.x *= inv; v.y *= inv; v.z *= inv; v.w *= inv;
    p[i] = v;
}

extern "C" void kernel_launch(void* const* d_in, const int* in_sizes, int n_in,
                              void* d_out, int out_size)
{
    const float* img   = (const float*)d_in[0];
    const float* gauss = (const float*)d_in[1];
    const float* sobel = (const float*)d_in[2];
    float* out = (float*)d_out;
    (void)sobel;

    dim3 grid(8, 16, 32);
    edge_pass1<<<grid, NTHREADS>>>(img, gauss, sobel, out);
    normalize_kernel<<<8192, 256>>>(out);
}

// round 15
// speedup vs baseline: 1.4052x; 1.4052x over previous
#include <cuda_runtime.h>

typedef unsigned long long u64;

#define NTHREADS 512
#define NBLOCKS  4096

#define RAW_S 76    // raw stride: 16B-aligned rows
#define HB_S  70    // stride for s_hb
#define T_S   136   // s_t stride in floats (34 float4 slots per row)

__device__ unsigned g_max_bits;   // zero-init; re-zeroed by last block each call
__device__ unsigned g_done;
__device__ unsigned g_max_final;

__device__ __forceinline__ u64 pk2(float x, float y){ u64 r; asm("mov.b64 %0,{%1,%2};":"=l"(r):"f"(x),"f"(y)); return r; }
__device__ __forceinline__ u64 add2(u64 a, u64 b){ u64 d; asm("add.rn.f32x2 %0,%1,%2;":"=l"(d):"l"(a),"l"(b)); return d; }
__device__ __forceinline__ u64 mul2(u64 a, u64 b){ u64 d; asm("mul.rn.f32x2 %0,%1,%2;":"=l"(d):"l"(a),"l"(b)); return d; }
__device__ __forceinline__ u64 fma2(u64 a, u64 b, u64 c){ u64 d; asm("fma.rn.f32x2 %0,%1,%2,%3;":"=l"(d):"l"(a),"l"(b),"l"(c)); return d; }
__device__ __forceinline__ u64 lds2(const float* p){ return *(const u64*)p; }

__device__ __forceinline__ void cp16(unsigned dst, const float* src, int sz){
    asm volatile("cp.async.cg.shared.global [%0], [%1], 16, %2;"
                 :: "r"(dst), "l"(src), "r"(sz));
}

__global__ void __launch_bounds__(NTHREADS, 3) edge_pass1(
    const float* __restrict__ img,
    const float* __restrict__ gauss,
    const float* __restrict__ sobel,
    float* __restrict__ out)
{
    __shared__ float s_raw[3][38 * RAW_S];  // triple-buffered raw tiles
    __shared__ float s_hb [38 * HB_S];      // h-gauss (img cols bx-1..bx+64)
    __shared__ float s_t  [32 * T_S];       // per (row, colpair): float4 {t1.lo,t1.hi,t2.lo,t2.hi}
    __shared__ float s_red[16];

    const int tid = threadIdx.x;
    const int bx = blockIdx.x << 6;
    const int by = blockIdx.y << 5;
    const int b  = blockIdx.z;
    const bool interior = (blockIdx.x - 1u < 6u) && (blockIdx.y - 1u < 14u);

    // gauss symmetric: g3=g1, g4=g0; sobel = [1,2,1]^T x [1,0,-1]
    const float g0 = __ldg(gauss + 0), g1 = __ldg(gauss + 1), g2 = __ldg(gauss + 2);
    const u64 g0p = pk2(g0, g0), g1p = pk2(g1, g1), g2p = pk2(g2, g2);
    const u64 m1p = pk2(-1.f, -1.f);

    const float* img_b = img + (((size_t)(b * 3)) << 18);

    auto load_raw = [&](int c) {
        unsigned rbase = (unsigned)__cvta_generic_to_shared(&s_raw[c][0]);
        const float* src = img_b + (((size_t)c) << 18);
        if (interior) {
            const float* base = src + ((by - 3) << 9) + bx - 4;
            #pragma unroll 2
            for (int i = tid; i < 684; i += NTHREADS) {
                int ry = i / 18, m = i - ry * 18;
                cp16(rbase + (unsigned)(ry * RAW_S + 4 * m) * 4u, base + (ry << 9) + 4 * m, 16);
            }
        } else {
            #pragma unroll 2
            for (int i = tid; i < 684; i += NTHREADS) {
                int ry = i / 18, m = i - ry * 18;
                int gy = by + ry - 3, gc = bx - 4 + 4 * m;
                bool ok = ((unsigned)gy < 512u) && ((unsigned)gc < 509u);
                const float* sp = ok ? (src + (gy << 9) + gc) : src;
                cp16(rbase + (unsigned)(ry * RAW_S + 4 * m) * 4u, sp, ok ? 16 : 0);
            }
        }
        asm volatile("cp.async.commit_group;");
    };

    // ---- stage-4 mapping: warp = rows {2w, 2w+1}; lane = output col pair (2l, 2l+1) ----
    const int s4_w = tid >> 5;         // 0..15
    const int s4_l = tid & 31;         // 0..31

    float acc00 = 0.f, acc01 = 0.f, acc10 = 0.f, acc11 = 0.f;

    auto s4_accum = [&]() {
        #pragma unroll
        for (int i = 0; i < 2; i++) {
            const float* p = s_t + (2 * s4_w + i) * T_S + 4 * s4_l;
            float4 A = *(const float4*)(p);
            float4 B = *(const float4*)(p + 4);
            float gx0 = A.x - B.x;                    // t1[c]   - t1[c+2]
            float gx1 = A.y - B.y;                    // t1[c+1] - t1[c+3]
            float gy0 = fmaf(2.f, A.w, A.z + B.z);    // t2[c] + 2 t2[c+1] + t2[c+2]
            float gy1 = fmaf(2.f, B.z, A.w + B.w);    // t2[c+1] + 2 t2[c+2] + t2[c+3]
            if (i == 0) {
                acc00 = fmaf(gx0, gx0, fmaf(gy0, gy0, acc00));
                acc01 = fmaf(gx1, gx1, fmaf(gy1, gy1, acc01));
            } else {
                acc10 = fmaf(gx0, gx0, fmaf(gy0, gy0, acc10));
                acc11 = fmaf(gx1, gx1, fmaf(gy1, gy1, acc11));
            }
        }
    };

    // prologue: issue ALL channel loads (3 groups outstanding)
    load_raw(0); load_raw(1); load_raw(2);

    #pragma unroll 1
    for (int c = 0; c < 3; c++) {
        if (c == 0)      asm volatile("cp.async.wait_group 2;");
        else if (c == 1) asm volatile("cp.async.wait_group 1;");
        else             asm volatile("cp.async.wait_group 0;");
        __syncthreads();          // bar1: raw[c] visible; S3(c-1) s_t writes visible

        // ---- fused region: S4(c-1) [reads s_t] + S2(c) [reads raw, writes hb] ----
        if (c > 0) s4_accum();

        if (tid < 418) {
            int ry = tid / 11;
            int c0 = (tid - ry * 11) * 6;
            const float* rp = &s_raw[c][0] + ry * RAW_S + c0;
            float w[12];
            #pragma unroll
            for (int u = 0; u < 6; u++) {
                float2 l = *(const float2*)(rp + 2 * u);
                w[2 * u] = l.x; w[2 * u + 1] = l.y;
            }
            float o[6];
            #pragma unroll
            for (int j = 0; j < 6; j++)
                o[j] = fmaf(g0, w[j + 1] + w[j + 5],
                       fmaf(g1, w[j + 2] + w[j + 4], g2 * w[j + 3]));
            float* hp = s_hb + ry * HB_S + c0;
            *(float2*)(hp)     = make_float2(o[0], o[1]);
            *(float2*)(hp + 2) = make_float2(o[2], o[3]);
            *(float2*)(hp + 4) = make_float2(o[4], o[5]);
        }
        __syncthreads();          // bar2: hb(c) visible; S4(c-1) s_t reads complete

        // ---- stage 3: vertical gaussian (+crop) + vertical sobel, interleaved STS.128 ----
        if (tid < 264) {
            int cb, r0;
            if (tid < 256) { cb = (tid & 31) << 1; r0 = (tid >> 5) << 2; }
            else           { cb = 64;              r0 = (tid - 256) << 2; }
            const float* hp = s_hb + r0 * HB_S + cb;
            u64 h[10];
            #pragma unroll
            for (int k = 0; k < 10; k++) h[k] = lds2(hp + k * HB_S);

            u64 cm = 0;
            if (!interior)
                cm = pk2(((unsigned)(bx + cb - 1) < 512u) ? 1.f : 0.f,
                         ((unsigned)(bx + cb)     < 512u) ? 1.f : 0.f);
            u64 bl[6];
            #pragma unroll
            for (int j = 0; j < 6; j++) {
                u64 s = fma2(g0p, add2(h[j], h[j + 4]),
                        fma2(g1p, add2(h[j + 1], h[j + 3]), mul2(g2p, h[j + 2])));
                if (!interior) {
                    s = mul2(s, cm);
                    if ((unsigned)(by + r0 - 1 + j) >= 512u) s = 0ull;
                }
                bl[j] = s;
            }
            float* tp = s_t + r0 * T_S + (cb << 1);
            #pragma unroll
            for (int j = 0; j < 4; j++) {
                u64 t1v = add2(add2(bl[j], bl[j + 2]), add2(bl[j + 1], bl[j + 1]));
                u64 t2v = fma2(bl[j + 2], m1p, bl[j]);
                ulonglong2 v; v.x = t1v; v.y = t2v;
                *(ulonglong2*)(tp + j * T_S) = v;     // STS.128 {t1.lo,t1.hi,t2.lo,t2.hi}
            }
        }
    }

    __syncthreads();              // s_t of channel 2 visible
    s4_accum();

    // ---- magnitude, store (2x STG.64, coalesced), block max ----
    float mloc;
    {
        float m00 = sqrtf(acc00), m01 = sqrtf(acc01);
        float m10 = sqrtf(acc10), m11 = sqrtf(acc11);
        size_t base = (((size_t)((b << 9) + by + 2 * s4_w)) << 9) + bx + 2 * s4_l;
        *(float2*)(out + base)       = make_float2(m00, m01);
        *(float2*)(out + base + 512) = make_float2(m10, m11);
        mloc = fmaxf(fmaxf(m00, m01), fmaxf(m10, m11));
    }
    #pragma unroll
    for (int o = 16; o; o >>= 1) mloc = fmaxf(mloc, __shfl_xor_sync(0xffffffffu, mloc, o));
    if ((tid & 31) == 0) s_red[tid >> 5] = mloc;
    __syncthreads();
    if (tid == 0) {
        float m = s_red[0];
        #pragma unroll
        for (int k = 1; k < 16; k++) m = fmaxf(m, s_red[k]);
        atomicMax(&g_max_bits, __float_as_uint(m));
        __threadfence();
        unsigned o = atomicAdd(&g_done, 1u);
        if (o == NBLOCKS - 1u) {
            g_max_final = g_max_bits;   // publish for normalize
            g_max_bits = 0u;            // reset for next graph replay
            g_done = 0u;
            __threadfence();
        }
    }
}

__global__ void __launch_bounds__(256) normalize_kernel(float* __restrict__ out)
{
    const float inv = 1.0f / __uint_as_float(g_max_final);
    float4* p = (float4*)out;
    int i = blockIdx.x * 256 + threadIdx.x;   // 8192 * 256 = 2^21 float4 exactly
    float4 v = p[i];
    v.x *= inv; v.y *= inv; v.z *= inv; v.w *= inv;
    p[i] = v;
}

extern "C" void kernel_launch(void* const* d_in, const int* in_sizes, int n_in,
                              void* d_out, int out_size)
{
    const float* img   = (const float*)d_in[0];
    const float* gauss = (const float*)d_in[1];
    const float* sobel = (const float*)d_in[2];
    float* out = (float*)d_out;
    (void)sobel;

    dim3 grid(8, 16, 32);
    edge_pass1<<<grid, NTHREADS>>>(img, gauss, sobel, out);
    normalize_kernel<<<8192, 256>>>(out);
}